// round 2
// baseline (speedup 1.0000x reference)
#include <cuda_runtime.h>
#include <cstdint>

// Problem constants
#define BSZ 128
#define SDIM 1024
#define AD 128
#define HH 512
#define KDIM (SDIM + AD)      // 1152 (fused [x_t, u_t] K dimension)
#define OUT_T (HH + 1)        // 513

// Tiling
#define MT 32                 // batch-tile per CTA
#define NT 32                 // n-tile per CTA
#define NCTA_M (BSZ / MT)     // 4
#define NCTA_N (SDIM / NT)    // 32
#define NCTA (NCTA_M * NCTA_N) // 128 CTAs (1 per SM, co-resident)
#define NTHREADS 128
#define KC 128                // k-chunk size
#define NCHUNK (KDIM / KC)    // 9 (8 x-chunks + 1 u-chunk)

// SMEM layout (padded to avoid bank conflicts)
#define WPAD 33
#define XPAD 132
#define WSM_FLOATS (KDIM * WPAD)        // 38016
#define XSM_FLOATS (MT * XPAD)          // 4224
#define SMEM_BYTES ((WSM_FLOATS + 2 * XSM_FLOATS) * 4)  // 185856 B

// Software grid barrier state (persists across graph replays; epochs are
// monotonic, base is re-read each launch).
__device__ unsigned g_arrive[NCTA];
__device__ unsigned g_release;

__device__ __forceinline__ void grid_barrier(unsigned epoch, int bid, int tid)
{
    __syncthreads();
    if (tid == 0) {
        __threadfence();
        *((volatile unsigned*)&g_arrive[bid]) = epoch;
    }
    if (bid == 0) {
        // 128 threads each poll one CTA's slot
        while ((int)(*((volatile unsigned*)&g_arrive[tid]) - epoch) < 0) { }
        __syncthreads();
        if (tid == 0) {
            __threadfence();
            *((volatile unsigned*)&g_release) = epoch;
        }
    } else if (tid == 0) {
        while ((int)(*((volatile unsigned*)&g_release) - epoch) < 0) { }
    }
    __syncthreads();
    __threadfence();
}

__device__ __forceinline__ uint32_t f2tf32(float v)
{
    uint32_t r;
    asm volatile("cvt.rna.tf32.f32 %0, %1;" : "=r"(r) : "f"(v));
    return r;
}

__device__ __forceinline__ void mma_tf32(float* d,
                                         uint32_t a0, uint32_t a1, uint32_t a2, uint32_t a3,
                                         uint32_t b0, uint32_t b1)
{
    asm volatile("mma.sync.aligned.m16n8k8.row.col.f32.tf32.tf32.f32 "
                 "{%0,%1,%2,%3}, {%4,%5,%6,%7}, {%8,%9}, {%0,%1,%2,%3};"
                 : "+f"(d[0]), "+f"(d[1]), "+f"(d[2]), "+f"(d[3])
                 : "r"(a0), "r"(a1), "r"(a2), "r"(a3), "r"(b0), "r"(b1));
}

// Async-load one 32x128 fp32 chunk of [x_t | u_t] into padded smem.
__device__ __forceinline__ void cp_chunk(float* dstsm, const float* __restrict__ out,
                                         const float* __restrict__ u,
                                         int t, int m0, int kc, int tid)
{
#pragma unroll
    for (int j = 0; j < 8; j++) {
        int e = tid + j * NTHREADS;      // 0..1023 float4 slots
        int row = e >> 5;                // 0..31 (local batch row)
        int c4 = e & 31;                 // float4 column within chunk
        const float* src;
        if (kc < 8) {
            // x_t lives at out[:, t, :]
            src = out + ((size_t)(m0 + row) * OUT_T + t) * SDIM + kc * KC + c4 * 4;
        } else {
            src = u + ((size_t)(m0 + row) * HH + t) * AD + c4 * 4;
        }
        uint32_t sdst = (uint32_t)__cvta_generic_to_shared(dstsm + row * XPAD + c4 * 4);
        asm volatile("cp.async.cg.shared.global [%0], [%1], 16;"
                     :: "r"(sdst), "l"(src) : "memory");
    }
}

extern "C" __global__ void __launch_bounds__(NTHREADS, 1)
ssm_persistent_kernel(const float* __restrict__ x0, const float* __restrict__ u,
                      const float* __restrict__ A, const float* __restrict__ Bm,
                      float* __restrict__ out)
{
    extern __shared__ float smem[];
    float* wsm = smem;                         // [KDIM][WPAD] tf32 weight slice
    float* xsm0 = smem + WSM_FLOATS;           // [MT][XPAD]
    float* xsm1 = xsm0 + XSM_FLOATS;

    const int tid = threadIdx.x;
    const int bid = blockIdx.x;
    const int mt = bid & (NCTA_M - 1);
    const int nt = bid >> 2;
    const int m0 = mt * MT;
    const int n0 = nt * NT;
    const int w = tid >> 5;
    const int lane = tid & 31;
    const int wm = w & 1;     // m-strip (16 rows)
    const int wn = w >> 1;    // n-strip (16 cols)

    // Barrier epoch base for this launch (quiescent value from previous launch).
    const unsigned base = *((volatile unsigned*)&g_release);

    // ---- One-time: load fused weight slice W[k][nl] = (k<S ? A[n,k] : B[n,k-S]),
    //      rounded to tf32. Resident in SMEM for the whole rollout. ----
    uint32_t* wsmu = (uint32_t*)wsm;
    for (int i = tid; i < KDIM * NT; i += NTHREADS) {
        int k = i >> 5;
        int nl = i & 31;
        float v = (k < SDIM) ? A[(size_t)(n0 + nl) * SDIM + k]
                             : Bm[(size_t)(n0 + nl) * AD + (k - SDIM)];
        wsmu[k * WPAD + nl] = f2tf32(v);
    }

    // ---- x0 -> out[:, 0, :] (grid-strided float4 copy) ----
    for (int i = bid * NTHREADS + tid; i < BSZ * SDIM / 4; i += NCTA * NTHREADS) {
        int b = i >> 8;          // 256 float4 per batch row
        int s4 = i & 255;
        float4 v = ((const float4*)x0)[i];
        ((float4*)(out + (size_t)b * OUT_T * SDIM))[s4] = v;
    }

    grid_barrier(base + 1, bid, tid);

    // ---- 512 sequential steps ----
    for (int t = 0; t < HH; t++) {
        float d[2][4];
#pragma unroll
        for (int nn = 0; nn < 2; nn++)
#pragma unroll
            for (int q = 0; q < 4; q++) d[nn][q] = 0.0f;

        cp_chunk(xsm0, out, u, t, m0, 0, tid);
        asm volatile("cp.async.commit_group;" ::: "memory");

        for (int kc = 0; kc < NCHUNK; kc++) {
            float* cur = (kc & 1) ? xsm1 : xsm0;
            float* nxt = (kc & 1) ? xsm0 : xsm1;
            if (kc + 1 < NCHUNK) {
                cp_chunk(nxt, out, u, t, m0, kc + 1, tid);
                asm volatile("cp.async.commit_group;" ::: "memory");
                asm volatile("cp.async.wait_group 1;" ::: "memory");
            } else {
                asm volatile("cp.async.wait_group 0;" ::: "memory");
            }
            __syncthreads();

            const uint32_t* xs = (const uint32_t*)cur;
            const int r = wm * 16 + (lane >> 2);
            const int cbase = lane & 3;
            const int nb = wn * 16 + (lane >> 2);
#pragma unroll
            for (int kt = 0; kt < KC / 8; kt++) {
                int c = kt * 8 + cbase;
                uint32_t a0 = f2tf32(__uint_as_float(xs[r * XPAD + c]));
                uint32_t a1 = f2tf32(__uint_as_float(xs[(r + 8) * XPAD + c]));
                uint32_t a2 = f2tf32(__uint_as_float(xs[r * XPAD + c + 4]));
                uint32_t a3 = f2tf32(__uint_as_float(xs[(r + 8) * XPAD + c + 4]));
                int kg = kc * KC + kt * 8 + cbase;
#pragma unroll
                for (int nn = 0; nn < 2; nn++) {
                    uint32_t b0 = wsmu[kg * WPAD + nb + nn * 8];
                    uint32_t b1 = wsmu[(kg + 4) * WPAD + nb + nn * 8];
                    mma_tf32(d[nn], a0, a1, a2, a3, b0, b1);
                }
            }
            __syncthreads();
        }

        // Write x_{t+1} tile to out[:, t+1, :]
        const int rr = m0 + wm * 16 + (lane >> 2);
        const int cc = n0 + wn * 16 + 2 * (lane & 3);
        float* dst = out + (size_t)(t + 1) * SDIM;
#pragma unroll
        for (int nn = 0; nn < 2; nn++) {
            float2 v01 = make_float2(d[nn][0], d[nn][1]);
            float2 v23 = make_float2(d[nn][2], d[nn][3]);
            *(float2*)(dst + (size_t)rr * OUT_T * SDIM + cc + nn * 8) = v01;
            *(float2*)(dst + (size_t)(rr + 8) * OUT_T * SDIM + cc + nn * 8) = v23;
        }

        grid_barrier(base + 2 + t, bid, tid);
    }
}

extern "C" void kernel_launch(void* const* d_in, const int* in_sizes, int n_in,
                              void* d_out, int out_size)
{
    const float* x0 = (const float*)d_in[0];
    const float* u  = (const float*)d_in[1];
    const float* A  = (const float*)d_in[2];
    const float* Bm = (const float*)d_in[3];
    float* out = (float*)d_out;

    // Idempotent, not a stream op — safe under graph capture.
    cudaFuncSetAttribute(ssm_persistent_kernel,
                         cudaFuncAttributeMaxDynamicSharedMemorySize, SMEM_BYTES);

    ssm_persistent_kernel<<<NCTA, NTHREADS, SMEM_BYTES>>>(x0, u, A, Bm, out);
}

// round 3
// speedup vs baseline: 1.0239x; 1.0239x over previous
#include <cuda_runtime.h>
#include <cstdint>

// Problem constants
#define BSZ 128
#define SDIM 1024
#define AD 128
#define HH 512
#define KDIM 1152
#define OUT_T 513

// Grid/tiling
#define NCTA 128
#define NTHREADS 256
#define MT 32                 // batch tile per CTA
#define NT 32                 // s-output tile per CTA
#define KG 4                  // K-split groups (288 each)
#define KSLICE (KDIM / KG)    // 288
#define NOCT (KDIM / 8)       // 144 octets
#define WOCT (KSLICE / 8)     // 36 octets per warp

// SMEM layout (in 32-bit words)
// xlo[o][b][4] : k = 8o + {0..3}; xhi[o][b][4] : k = 8o + {4..7}
#define XHALF_W (NOCT * MT * 4)       // 18432 words = 73728 B
#define XS_WORDS (2 * XHALF_W)        // 36864
#define RED_STRIDE 40                 // padded row (16 rows x 40 words per warp)
#define RED_W (8 * 16 * RED_STRIDE)   // 5120 words
#define SMEM_BYTES ((XS_WORDS + RED_W) * 4)   // 167936 B

// Software grid-barrier state (zero-init; epochs monotonic across replays)
__device__ unsigned g_arrive[NCTA];
__device__ unsigned g_release;

// Scratch (allowed: __device__ globals). xbuf: tf32 state double buffer.
// ubuf: tf32 u re-laid-out [t][b][ad].
__device__ __align__(16) uint32_t g_xbuf[2][BSZ * SDIM];
__device__ __align__(16) uint32_t g_ubuf[HH * BSZ * AD];

__device__ __forceinline__ void grid_barrier(unsigned epoch, int bid, int tid)
{
    __syncthreads();
    if (tid == 0) {
        __threadfence();
        *((volatile unsigned*)&g_arrive[bid]) = epoch;
    }
    if (bid == 0) {
        if (tid < NCTA) {
            while ((int)(*((volatile unsigned*)&g_arrive[tid]) - epoch) < 0) { }
        }
        __syncthreads();
        if (tid == 0) {
            __threadfence();
            *((volatile unsigned*)&g_release) = epoch;
        }
    } else if (tid == 0) {
        while ((int)(*((volatile unsigned*)&g_release) - epoch) < 0) { }
    }
    __syncthreads();
    __threadfence();
}

__device__ __forceinline__ uint32_t f2tf32(float v)
{
    uint32_t r;
    asm("cvt.rna.tf32.f32 %0, %1;" : "=r"(r) : "f"(v));
    return r;
}

__device__ __forceinline__ void mma_tf32(float* d,
                                         uint32_t a0, uint32_t a1, uint32_t a2, uint32_t a3,
                                         uint32_t b0, uint32_t b1)
{
    asm volatile("mma.sync.aligned.m16n8k8.row.col.f32.tf32.tf32.f32 "
                 "{%0,%1,%2,%3}, {%4,%5,%6,%7}, {%8,%9}, {%0,%1,%2,%3};"
                 : "+f"(d[0]), "+f"(d[1]), "+f"(d[2]), "+f"(d[3])
                 : "r"(a0), "r"(a1), "r"(a2), "r"(a3), "r"(b0), "r"(b1));
}

__device__ __forceinline__ void cp16(uint32_t dst_smem, const void* src)
{
    asm volatile("cp.async.cg.shared.global [%0], [%1], 16;"
                 :: "r"(dst_smem), "l"(src) : "memory");
}

__device__ __forceinline__ float wv(const float* __restrict__ A,
                                    const float* __restrict__ Bm, int s, int k)
{
    return (k < SDIM) ? A[(size_t)s * SDIM + k] : Bm[(size_t)s * AD + (k - SDIM)];
}

// Issue u chunks for step t into smem octets 128..143 (4 x 16B per thread).
__device__ __forceinline__ void issue_u(int t, int m0, int tid, uint32_t xsb)
{
    const uint32_t* usrc = g_ubuf + ((size_t)t * BSZ + m0) * AD;
#pragma unroll
    for (int it = 0; it < 4; it++) {
        int q = tid + it * NTHREADS;          // 0..1023
        int b = q >> 5;                       // 0..31
        int kq = q & 31;                      // 16B chunk within 128-wide row
        uint32_t dst = xsb + ((kq & 1) ? (XHALF_W * 4) : 0)
                     + (((128 + (kq >> 1)) * MT + b) << 4);
        cp16(dst, usrc + (size_t)b * AD + kq * 4);
    }
}

extern "C" __global__ void __launch_bounds__(NTHREADS, 1)
ssm_v3_kernel(const float* __restrict__ x0, const float* __restrict__ u,
              const float* __restrict__ A, const float* __restrict__ Bm,
              float* __restrict__ out)
{
    extern __shared__ uint32_t sm[];
    float* smf = (float*)sm;
    float* red = smf + XS_WORDS;

    const int tid = threadIdx.x;
    const int bid = blockIdx.x;
    const int m0 = (bid & 3) * MT;
    const int n0 = (bid >> 2) * NT;
    const int w = tid >> 5;
    const int lane = tid & 31;
    const int g = lane >> 2;      // 0..7
    const int c = lane & 3;       // 0..3
    const int ss = w & 1;         // s-strip (16 rows of output-s)
    const int kg = w >> 1;        // k-group (288 wide)
    const int gtid = bid * NTHREADS + tid;

    const unsigned base = *((volatile unsigned*)&g_release);

    // ---- init: u -> tf32 ubuf[t][b][ad] ----
    for (int j = gtid; j < HH * BSZ * (AD / 4); j += NCTA * NTHREADS) {
        int ad4 = j & 31;
        int b = (j >> 5) & 127;
        int t = j >> 12;
        float4 v = *(const float4*)(u + ((size_t)b * HH + t) * AD + ad4 * 4);
        uint4 o4 = make_uint4(f2tf32(v.x), f2tf32(v.y), f2tf32(v.z), f2tf32(v.w));
        *(uint4*)(g_ubuf + ((size_t)t * BSZ + b) * AD + ad4 * 4) = o4;
    }
    // ---- init: xbuf[0] = tf32(x0); out[:,0,:] = x0 ----
    for (int j = gtid; j < BSZ * (SDIM / 4); j += NCTA * NTHREADS) {
        int b = j >> 8;
        int s4 = j & 255;
        float4 v = ((const float4*)x0)[j];
        ((float4*)out)[(size_t)b * OUT_T * (SDIM / 4) + s4] = v;
        uint4 o4 = make_uint4(f2tf32(v.x), f2tf32(v.y), f2tf32(v.z), f2tf32(v.w));
        *(uint4*)(g_xbuf[0] + (size_t)j * 4) = o4;
    }

    // ---- weights into registers (invariant across all 512 steps) ----
    uint32_t a[WOCT][4];
    {
        const int srow = n0 + ss * 16 + g;
#pragma unroll
        for (int i = 0; i < WOCT; i++) {
            int k0 = kg * KSLICE + i * 8 + c;
            a[i][0] = f2tf32(wv(A, Bm, srow, k0));
            a[i][1] = f2tf32(wv(A, Bm, srow + 8, k0));
            a[i][2] = f2tf32(wv(A, Bm, srow, k0 + 4));
            a[i][3] = f2tf32(wv(A, Bm, srow + 8, k0 + 4));
        }
    }

    unsigned epoch = base + 1;
    grid_barrier(epoch, bid, tid);
    epoch++;

    const uint32_t xsb = (uint32_t)__cvta_generic_to_shared(sm);

    // u chunks for t=0
    issue_u(0, m0, tid, xsb);
    asm volatile("cp.async.commit_group;" ::: "memory");

    for (int t = 0; t < HH; t++) {
        // ---- stage x_t (tf32) into smem: 8192 x 16B chunks ----
        {
            const uint32_t* xsrc = g_xbuf[t & 1] + (size_t)m0 * SDIM;
#pragma unroll 8
            for (int it = 0; it < 32; it++) {
                int q = tid + it * NTHREADS;     // 0..8191
                int b = q >> 8;                  // 0..31
                int kq = q & 255;                // 16B chunk in 1024-wide row
                uint32_t dst = xsb + ((kq & 1) ? (XHALF_W * 4) : 0)
                             + (((kq >> 1) * MT + b) << 4);
                cp16(dst, xsrc + (size_t)b * SDIM + kq * 4);
            }
        }
        asm volatile("cp.async.commit_group;" ::: "memory");
        asm volatile("cp.async.wait_group 0;" ::: "memory");
        __syncthreads();

        // ---- MMA mainloop: D[s16][b32] over this warp's 288-k slice ----
        float d[4][4];
#pragma unroll
        for (int nn = 0; nn < 4; nn++)
#pragma unroll
            for (int q = 0; q < 4; q++) d[nn][q] = 0.0f;

        const int wbase = kg * (WOCT * 128) + g * 4 + c;  // word idx of (o=kg*36, b=g, c)
#pragma unroll
        for (int i = 0; i < WOCT; i++) {
#pragma unroll
            for (int nn = 0; nn < 4; nn++) {
                uint32_t blo = sm[wbase + i * 128 + nn * 32];
                uint32_t bhi = sm[wbase + i * 128 + nn * 32 + XHALF_W];
                mma_tf32(d[nn], a[i][0], a[i][1], a[i][2], a[i][3], blo, bhi);
            }
        }
        __syncthreads();

        // ---- prefetch u for t+1 (hides behind epilogue + barrier) ----
        if (t + 1 < HH) issue_u(t + 1, m0, tid, xsb);
        asm volatile("cp.async.commit_group;" ::: "memory");

        // ---- partials to smem ----
        {
            int rb = w * (16 * RED_STRIDE) + g * RED_STRIDE + 2 * c;
#pragma unroll
            for (int nn = 0; nn < 4; nn++) {
                *(float2*)(red + rb + nn * 8) = make_float2(d[nn][0], d[nn][1]);
                *(float2*)(red + rb + 8 * RED_STRIDE + nn * 8) = make_float2(d[nn][2], d[nn][3]);
            }
        }
        __syncthreads();

        // ---- reduce 4 k-partials; write fp32 out + tf32 xbuf ----
        {
            int b = tid >> 3;               // 0..31
            int s4 = (tid & 7) * 4;         // 0..28
            int ssr = s4 >> 4;              // s-strip
            float acc0 = 0.f, acc1 = 0.f, acc2 = 0.f, acc3 = 0.f;
#pragma unroll
            for (int kk = 0; kk < 4; kk++) {
                int wb = (kk * 2 + ssr) * (16 * RED_STRIDE) + b;
                acc0 += red[wb + ((s4 + 0) & 15) * RED_STRIDE];
                acc1 += red[wb + ((s4 + 1) & 15) * RED_STRIDE];
                acc2 += red[wb + ((s4 + 2) & 15) * RED_STRIDE];
                acc3 += red[wb + ((s4 + 3) & 15) * RED_STRIDE];
            }
            float* op = out + ((size_t)(m0 + b) * OUT_T + (t + 1)) * SDIM + n0 + s4;
            *(float4*)op = make_float4(acc0, acc1, acc2, acc3);

            uint32_t* xp = g_xbuf[(t + 1) & 1] + (size_t)(m0 + b) * SDIM + n0 + s4;
            uint32_t t0 = f2tf32(acc0), t1 = f2tf32(acc1), t2 = f2tf32(acc2), t3 = f2tf32(acc3);
            asm volatile("st.global.cg.v4.b32 [%0], {%1,%2,%3,%4};"
                         :: "l"(xp), "r"(t0), "r"(t1), "r"(t2), "r"(t3) : "memory");
        }

        grid_barrier(epoch, bid, tid);
        epoch++;
    }
}

extern "C" void kernel_launch(void* const* d_in, const int* in_sizes, int n_in,
                              void* d_out, int out_size)
{
    const float* x0 = (const float*)d_in[0];
    const float* u  = (const float*)d_in[1];
    const float* A  = (const float*)d_in[2];
    const float* Bm = (const float*)d_in[3];
    float* out = (float*)d_out;

    cudaFuncSetAttribute(ssm_v3_kernel,
                         cudaFuncAttributeMaxDynamicSharedMemorySize, SMEM_BYTES);

    ssm_v3_kernel<<<NCTA, NTHREADS, SMEM_BYTES>>>(x0, u, A, Bm, out);
}

// round 4
// speedup vs baseline: 1.9299x; 1.8848x over previous
#include <cuda_runtime.h>
#include <cstdint>

// Problem constants
#define BSZ 128
#define SDIM 1024
#define AD 128
#define HH 512
#define KDIM 1152
#define OUT_T 513

// Grid/tiling
#define NCTA 128
#define NTHREADS 256
#define CLUSTER 4
#define MT 32                 // batch tile per CTA
#define NT 32                 // s-output tile per CTA
#define KG 4                  // K-split groups (288 each)
#define KSLICE (KDIM / KG)    // 288
#define NOCT (KDIM / 8)       // 144 octets total (128 x + 16 u)
#define WOCT (KSLICE / 8)     // 36 octets per warp

// SMEM layout (32-bit words). Per half h: [o 0..143][b 0..31][4 words],
// word(k,b) with k = o*8 + h*4 + c  ->  h*XHALF_W + o*128 + b*4 + c.
#define XHALF_W (NOCT * MT * 4)       // 18432 words = 73728 B
#define XS_WORDS (2 * XHALF_W)        // 36864 words
#define RED_STRIDE 40
#define RED_W (8 * 16 * RED_STRIDE)   // 5120 words
#define MBAR_OFF_W (XS_WORDS + RED_W) // word offset of mbarrier (8B aligned)
#define SMEM_BYTES ((MBAR_OFF_W + 4) * 4)

// Per-step, per-CTA staged bytes: x = 2*128*32*16 = 131072, u = 2*16*32*16 = 16384
#define X_SLICE_BYTES 131072
#define U_SLICE_BYTES 16384
#define STEP_TX (X_SLICE_BYTES + U_SLICE_BYTES)   // 147456

// Software grid-barrier state (zero-init; epochs monotonic across replays)
__device__ unsigned g_arrive[NCTA];
__device__ unsigned g_release;

// tf32 state double buffer in MMA-smem layout: [buf][mt][half][o 0..127][b][4]
__device__ __align__(16) uint32_t g_xbuf[2][4 * 2 * 128 * MT * 4];
// tf32 drive in MMA-smem layout: [t][mt][half][o 0..15][b][4]
__device__ __align__(16) uint32_t g_ubuf[HH * 4 * 2 * 16 * MT * 4];

__device__ __forceinline__ void grid_barrier(unsigned epoch, int bid, int tid)
{
    __syncthreads();
    if (tid == 0) {
        __threadfence();
        *((volatile unsigned*)&g_arrive[bid]) = epoch;
    }
    if (bid == 0) {
        if (tid < NCTA) {
            while ((int)(*((volatile unsigned*)&g_arrive[tid]) - epoch) < 0) { }
        }
        __syncthreads();
        if (tid == 0) {
            __threadfence();
            *((volatile unsigned*)&g_release) = epoch;
        }
    } else if (tid == 0) {
        while ((int)(*((volatile unsigned*)&g_release) - epoch) < 0) { }
    }
    __syncthreads();
    __threadfence();
}

__device__ __forceinline__ uint32_t f2tf32(float v)
{
    uint32_t r;
    asm("cvt.rna.tf32.f32 %0, %1;" : "=r"(r) : "f"(v));
    return r;
}

__device__ __forceinline__ void mma_tf32(float* d,
                                         uint32_t a0, uint32_t a1, uint32_t a2, uint32_t a3,
                                         uint32_t b0, uint32_t b1)
{
    asm volatile("mma.sync.aligned.m16n8k8.row.col.f32.tf32.tf32.f32 "
                 "{%0,%1,%2,%3}, {%4,%5,%6,%7}, {%8,%9}, {%0,%1,%2,%3};"
                 : "+f"(d[0]), "+f"(d[1]), "+f"(d[2]), "+f"(d[3])
                 : "r"(a0), "r"(a1), "r"(a2), "r"(a3), "r"(b0), "r"(b1));
}

__device__ __forceinline__ void bulk_mc(uint32_t dst_smem, const void* src,
                                        uint32_t bytes, uint32_t mbar, uint16_t mask)
{
    asm volatile("cp.async.bulk.shared::cluster.global.mbarrier::complete_tx::bytes"
                 ".multicast::cluster [%0], [%1], %2, [%3], %4;"
                 :: "r"(dst_smem), "l"(src), "r"(bytes), "r"(mbar), "h"(mask)
                 : "memory");
}

__device__ __forceinline__ void mbar_wait(uint32_t mbar, uint32_t parity)
{
    uint32_t done;
    asm volatile("{\n\t.reg .pred p;\n\t"
                 "mbarrier.try_wait.parity.acquire.cta.shared::cta.b64 p, [%1], %2;\n\t"
                 "selp.b32 %0, 1, 0, p;\n\t}"
                 : "=r"(done) : "r"(mbar), "r"(parity) : "memory");
    if (!done) {
        asm volatile("{\n\t.reg .pred P1;\n\t"
                     "W%=:\n\t"
                     "mbarrier.try_wait.parity.acquire.cta.shared::cta.b64 P1, [%0], %1, 0x989680;\n\t"
                     "@P1 bra.uni D%=;\n\t"
                     "bra.uni W%=;\n\t"
                     "D%=:\n\t}"
                     :: "r"(mbar), "r"(parity) : "memory");
    }
}

__device__ __forceinline__ float wv(const float* __restrict__ A,
                                    const float* __restrict__ Bm, int s, int k)
{
    return (k < SDIM) ? A[(size_t)s * SDIM + k] : Bm[(size_t)s * AD + (k - SDIM)];
}

extern "C" __global__ void __launch_bounds__(NTHREADS, 1) __cluster_dims__(CLUSTER, 1, 1)
ssm_v4_kernel(const float* __restrict__ x0, const float* __restrict__ u,
              const float* __restrict__ A, const float* __restrict__ Bm,
              float* __restrict__ out)
{
    extern __shared__ uint32_t sm[];
    float* red = (float*)(sm + XS_WORDS);

    const int tid = threadIdx.x;
    const int bid = blockIdx.x;
    // cluster ranks (consecutive bids) share the same m-tile
    const int mt = bid >> 5;
    const int nt = bid & 31;
    const int m0 = mt * MT;
    const int n0 = nt * NT;
    const int w = tid >> 5;
    const int lane = tid & 31;
    const int g = lane >> 2;      // 0..7
    const int c = lane & 3;       // 0..3
    const int ss = w & 1;         // s-strip
    const int kg = w >> 1;        // k-group
    const int gtid = bid * NTHREADS + tid;

    uint32_t rank;
    asm("mov.u32 %0, %%cluster_ctarank;" : "=r"(rank));

    const uint32_t smb = (uint32_t)__cvta_generic_to_shared(sm);
    const uint32_t mbar = smb + MBAR_OFF_W * 4;

    const unsigned base = *((volatile unsigned*)&g_release);

    if (tid == 0) {
        asm volatile("mbarrier.init.shared.b64 [%0], %1;" :: "r"(mbar), "r"(1) : "memory");
    }
    __syncthreads();
    asm volatile("barrier.cluster.arrive.aligned;" ::: "memory");
    asm volatile("barrier.cluster.wait.aligned;" ::: "memory");

    // ---- init: u -> tf32 ubuf in MMA layout [t][mt][half][o'][bl][4] ----
    for (int j = gtid; j < HH * BSZ * (AD / 4); j += NCTA * NTHREADS) {
        int a4 = j & 31;              // 4-float chunk within ad
        int b = (j >> 5) & 127;
        int t = j >> 12;
        float4 v = *(const float4*)(u + ((size_t)b * HH + t) * AD + a4 * 4);
        uint4 o4 = make_uint4(f2tf32(v.x), f2tf32(v.y), f2tf32(v.z), f2tf32(v.w));
        int umt = b >> 5, bl = b & 31;
        size_t widx = ((size_t)t * 4 + umt) * 4096 + (size_t)(a4 & 1) * 2048
                    + (size_t)(a4 >> 1) * 128 + (size_t)bl * 4;
        *(uint4*)(g_ubuf + widx) = o4;
    }
    // ---- init: xbuf[0] = tf32(x0) in MMA layout; out[:,0,:] = x0 ----
    for (int j = gtid; j < BSZ * (SDIM / 4); j += NCTA * NTHREADS) {
        int s4 = j & 255;             // 4-float chunk within s
        int b = j >> 8;
        float4 v = ((const float4*)x0)[j];
        ((float4*)out)[(size_t)b * OUT_T * (SDIM / 4) + s4] = v;
        uint4 o4 = make_uint4(f2tf32(v.x), f2tf32(v.y), f2tf32(v.z), f2tf32(v.w));
        int xmt = b >> 5, bl = b & 31;
        size_t widx = (size_t)xmt * 32768 + (size_t)(s4 & 1) * 16384
                    + (size_t)(s4 >> 1) * 128 + (size_t)bl * 4;
        *(uint4*)(g_xbuf[0] + widx) = o4;
    }

    // ---- weights into registers (invariant across all 512 steps) ----
    uint32_t a[WOCT][4];
    {
        const int srow = n0 + ss * 16 + g;
#pragma unroll
        for (int i = 0; i < WOCT; i++) {
            int k0 = kg * KSLICE + i * 8 + c;
            a[i][0] = f2tf32(wv(A, Bm, srow, k0));
            a[i][1] = f2tf32(wv(A, Bm, srow + 8, k0));
            a[i][2] = f2tf32(wv(A, Bm, srow, k0 + 4));
            a[i][3] = f2tf32(wv(A, Bm, srow + 8, k0 + 4));
        }
    }

    unsigned epoch = base + 1;
    grid_barrier(epoch, bid, tid);
    epoch++;

    const uint16_t mask = (1u << CLUSTER) - 1u;   // 0xF

    for (int t = 0; t < HH; t++) {
        // ---- stage x_t + u_t via multicast bulk (cooperative 1/4 slices) ----
        if (tid == 0) {
            asm volatile("mbarrier.arrive.expect_tx.shared.b64 _, [%0], %1;"
                         :: "r"(mbar), "r"((uint32_t)STEP_TX) : "memory");
            // x slice: rank r copies bytes [r*32768, (r+1)*32768) of the mt block
            {
                const uint32_t* src = g_xbuf[t & 1] + (size_t)mt * 32768 + rank * 8192;
                int half = rank >> 1, part = rank & 1;
                uint32_t dst = smb + half * (XHALF_W * 4) + part * 32768;
                bulk_mc(dst, src, 32768, mbar, mask);
            }
            // u slice: rank r copies bytes [r*4096, (r+1)*4096)
            {
                const uint32_t* src = g_ubuf + ((size_t)t * 4 + mt) * 4096 + rank * 1024;
                int half = rank >> 1, q = rank & 1;
                uint32_t dst = smb + half * (XHALF_W * 4) + 65536 + q * 4096;
                bulk_mc(dst, src, 4096, mbar, mask);
            }
        }
        mbar_wait(mbar, (uint32_t)(t & 1));

        // ---- MMA mainloop: D[s16][b32] over this warp's 288-k slice ----
        float d[4][4];
#pragma unroll
        for (int nn = 0; nn < 4; nn++)
#pragma unroll
            for (int q = 0; q < 4; q++) d[nn][q] = 0.0f;

        const int wbase = kg * (WOCT * 128) + g * 4 + c;
#pragma unroll
        for (int i = 0; i < WOCT; i++) {
#pragma unroll
            for (int nn = 0; nn < 4; nn++) {
                uint32_t blo = sm[wbase + i * 128 + nn * 32];
                uint32_t bhi = sm[wbase + i * 128 + nn * 32 + XHALF_W];
                mma_tf32(d[nn], a[i][0], a[i][1], a[i][2], a[i][3], blo, bhi);
            }
        }

        // ---- partials to smem ----
        {
            int rb = w * (16 * RED_STRIDE) + g * RED_STRIDE + 2 * c;
#pragma unroll
            for (int nn = 0; nn < 4; nn++) {
                *(float2*)(red + rb + nn * 8) = make_float2(d[nn][0], d[nn][1]);
                *(float2*)(red + rb + 8 * RED_STRIDE + nn * 8) = make_float2(d[nn][2], d[nn][3]);
            }
        }
        __syncthreads();

        // ---- reduce 4 k-partials; write fp32 out + tf32 xbuf (MMA layout) ----
        {
            int b = tid >> 3;               // 0..31
            int s4 = (tid & 7) * 4;         // 0,4,..,28
            int ssr = s4 >> 4;
            float acc0 = 0.f, acc1 = 0.f, acc2 = 0.f, acc3 = 0.f;
#pragma unroll
            for (int kk = 0; kk < 4; kk++) {
                int wb = (kk * 2 + ssr) * (16 * RED_STRIDE) + b;
                acc0 += red[wb + ((s4 + 0) & 15) * RED_STRIDE];
                acc1 += red[wb + ((s4 + 1) & 15) * RED_STRIDE];
                acc2 += red[wb + ((s4 + 2) & 15) * RED_STRIDE];
                acc3 += red[wb + ((s4 + 3) & 15) * RED_STRIDE];
            }
            float* op = out + ((size_t)(m0 + b) * OUT_T + (t + 1)) * SDIM + n0 + s4;
            *(float4*)op = make_float4(acc0, acc1, acc2, acc3);

            int k = n0 + s4;
            size_t widx = (size_t)mt * 32768 + (size_t)((k >> 2) & 1) * 16384
                        + (size_t)(k >> 3) * 128 + (size_t)b * 4;
            uint32_t* xp = g_xbuf[(t + 1) & 1] + widx;
            uint32_t t0 = f2tf32(acc0), t1 = f2tf32(acc1), t2 = f2tf32(acc2), t3 = f2tf32(acc3);
            asm volatile("st.global.cg.v4.b32 [%0], {%1,%2,%3,%4};"
                         :: "l"(xp), "r"(t0), "r"(t1), "r"(t2), "r"(t3) : "memory");
        }

        grid_barrier(epoch, bid, tid);
        epoch++;
    }
}

extern "C" void kernel_launch(void* const* d_in, const int* in_sizes, int n_in,
                              void* d_out, int out_size)
{
    const float* x0 = (const float*)d_in[0];
    const float* u  = (const float*)d_in[1];
    const float* A  = (const float*)d_in[2];
    const float* Bm = (const float*)d_in[3];
    float* out = (float*)d_out;

    cudaFuncSetAttribute(ssm_v4_kernel,
                         cudaFuncAttributeMaxDynamicSharedMemorySize, SMEM_BYTES);

    ssm_v4_kernel<<<NCTA, NTHREADS, SMEM_BYTES>>>(x0, u, A, Bm, out);
}

// round 5
// speedup vs baseline: 2.0617x; 1.0683x over previous
#include <cuda_runtime.h>
#include <cstdint>

// Problem constants
#define BSZ 128
#define SDIM 1024
#define AD 128
#define HH 512
#define KDIM 1152
#define OUT_T 513

// Grid/tiling
#define NCTA 128
#define NTHREADS 256
#define CLUSTER 4
#define MT 32                 // batch tile per CTA
#define NT 32                 // s-output tile per CTA
#define KG 4                  // K-split groups (288 each)
#define KSLICE (KDIM / KG)    // 288
#define NOCT (KDIM / 8)       // 144 octets total (128 x + 16 u)
#define WOCT (KSLICE / 8)     // 36 octets per warp

// SMEM layout (32-bit words). Per half h: [o 0..143][b 0..31][4 words],
// word(k,b) with k = o*8 + h*4 + c  ->  h*XHALF_W + o*128 + b*4 + c.
#define XHALF_W (NOCT * MT * 4)       // 18432 words = 73728 B
#define XS_WORDS (2 * XHALF_W)        // 36864 words
#define RED_STRIDE 40
#define RED_W (8 * 16 * RED_STRIDE)   // 5120 words
#define MBAR_OFF_W (XS_WORDS + RED_W) // word offset of mbarrier (8B aligned)
#define SMEM_BYTES ((MBAR_OFF_W + 4) * 4)

// Per-step, per-CTA staged bytes: x = 2*128*32*16 = 131072, u = 2*16*32*16 = 16384
#define X_SLICE_BYTES 131072
#define U_SLICE_BYTES 16384
#define STEP_TX (X_SLICE_BYTES + U_SLICE_BYTES)   // 147456

// Software grid-barrier state (zero-init; epochs monotonic across replays)
__device__ unsigned g_arrive[NCTA];
__device__ unsigned g_release;

// tf32 state double buffer in MMA-smem layout: [buf][mt][half][o 0..127][b][4]
__device__ __align__(16) uint32_t g_xbuf[2][4 * 2 * 128 * MT * 4];
// tf32 drive in MMA-smem layout: [t][mt][half][o 0..15][b][4]
__device__ __align__(16) uint32_t g_ubuf[HH * 4 * 2 * 16 * MT * 4];

__device__ __forceinline__ void grid_barrier(unsigned epoch, int bid, int tid)
{
    __syncthreads();
    if (tid == 0) {
        __threadfence();
        *((volatile unsigned*)&g_arrive[bid]) = epoch;
    }
    if (bid == 0) {
        if (tid < NCTA) {
            while ((int)(*((volatile unsigned*)&g_arrive[tid]) - epoch) < 0) { }
        }
        __syncthreads();
        if (tid == 0) {
            __threadfence();
            *((volatile unsigned*)&g_release) = epoch;
        }
    } else if (tid == 0) {
        while ((int)(*((volatile unsigned*)&g_release) - epoch) < 0) { }
    }
    __syncthreads();
    __threadfence();
}

__device__ __forceinline__ uint32_t f2tf32(float v)
{
    uint32_t r;
    asm("cvt.rna.tf32.f32 %0, %1;" : "=r"(r) : "f"(v));
    return r;
}

__device__ __forceinline__ void mma_tf32(float* d,
                                         uint32_t a0, uint32_t a1, uint32_t a2, uint32_t a3,
                                         uint32_t b0, uint32_t b1)
{
    asm volatile("mma.sync.aligned.m16n8k8.row.col.f32.tf32.tf32.f32 "
                 "{%0,%1,%2,%3}, {%4,%5,%6,%7}, {%8,%9}, {%0,%1,%2,%3};"
                 : "+f"(d[0]), "+f"(d[1]), "+f"(d[2]), "+f"(d[3])
                 : "r"(a0), "r"(a1), "r"(a2), "r"(a3), "r"(b0), "r"(b1));
}

__device__ __forceinline__ void bulk_mc(uint32_t dst_smem, const void* src,
                                        uint32_t bytes, uint32_t mbar, uint16_t mask)
{
    asm volatile("cp.async.bulk.shared::cluster.global.mbarrier::complete_tx::bytes"
                 ".multicast::cluster [%0], [%1], %2, [%3], %4;"
                 :: "r"(dst_smem), "l"(src), "r"(bytes), "r"(mbar), "h"(mask)
                 : "memory");
}

__device__ __forceinline__ void mbar_wait(uint32_t mbar, uint32_t parity)
{
    uint32_t done;
    asm volatile("{\n\t.reg .pred p;\n\t"
                 "mbarrier.try_wait.parity.acquire.cta.shared::cta.b64 p, [%1], %2;\n\t"
                 "selp.b32 %0, 1, 0, p;\n\t}"
                 : "=r"(done) : "r"(mbar), "r"(parity) : "memory");
    if (!done) {
        asm volatile("{\n\t.reg .pred P1;\n\t"
                     "W%=:\n\t"
                     "mbarrier.try_wait.parity.acquire.cta.shared::cta.b64 P1, [%0], %1, 0x989680;\n\t"
                     "@P1 bra.uni D%=;\n\t"
                     "bra.uni W%=;\n\t"
                     "D%=:\n\t}"
                     :: "r"(mbar), "r"(parity) : "memory");
    }
}

__device__ __forceinline__ float wv(const float* __restrict__ A,
                                    const float* __restrict__ Bm, int s, int k)
{
    return (k < SDIM) ? A[(size_t)s * SDIM + k] : Bm[(size_t)s * AD + (k - SDIM)];
}

extern "C" __global__ void __launch_bounds__(NTHREADS, 1) __cluster_dims__(CLUSTER, 1, 1)
ssm_v4_kernel(const float* __restrict__ x0, const float* __restrict__ u,
              const float* __restrict__ A, const float* __restrict__ Bm,
              float* __restrict__ out)
{
    extern __shared__ uint32_t sm[];
    float* red = (float*)(sm + XS_WORDS);

    const int tid = threadIdx.x;
    const int bid = blockIdx.x;
    // cluster ranks (consecutive bids) share the same m-tile
    const int mt = bid >> 5;
    const int nt = bid & 31;
    const int m0 = mt * MT;
    const int n0 = nt * NT;
    const int w = tid >> 5;
    const int lane = tid & 31;
    const int g = lane >> 2;      // 0..7
    const int c = lane & 3;       // 0..3
    const int ss = w & 1;         // s-strip
    const int kg = w >> 1;        // k-group
    const int gtid = bid * NTHREADS + tid;

    uint32_t rank;
    asm("mov.u32 %0, %%cluster_ctarank;" : "=r"(rank));

    const uint32_t smb = (uint32_t)__cvta_generic_to_shared(sm);
    const uint32_t mbar = smb + MBAR_OFF_W * 4;

    const unsigned base = *((volatile unsigned*)&g_release);

    if (tid == 0) {
        asm volatile("mbarrier.init.shared.b64 [%0], %1;" :: "r"(mbar), "r"(1) : "memory");
    }
    __syncthreads();
    asm volatile("barrier.cluster.arrive.aligned;" ::: "memory");
    asm volatile("barrier.cluster.wait.aligned;" ::: "memory");

    // ---- init: u -> tf32 ubuf in MMA layout [t][mt][half][o'][bl][4] ----
    for (int j = gtid; j < HH * BSZ * (AD / 4); j += NCTA * NTHREADS) {
        int a4 = j & 31;              // 4-float chunk within ad
        int b = (j >> 5) & 127;
        int t = j >> 12;
        float4 v = *(const float4*)(u + ((size_t)b * HH + t) * AD + a4 * 4);
        uint4 o4 = make_uint4(f2tf32(v.x), f2tf32(v.y), f2tf32(v.z), f2tf32(v.w));
        int umt = b >> 5, bl = b & 31;
        size_t widx = ((size_t)t * 4 + umt) * 4096 + (size_t)(a4 & 1) * 2048
                    + (size_t)(a4 >> 1) * 128 + (size_t)bl * 4;
        *(uint4*)(g_ubuf + widx) = o4;
    }
    // ---- init: xbuf[0] = tf32(x0) in MMA layout; out[:,0,:] = x0 ----
    for (int j = gtid; j < BSZ * (SDIM / 4); j += NCTA * NTHREADS) {
        int s4 = j & 255;             // 4-float chunk within s
        int b = j >> 8;
        float4 v = ((const float4*)x0)[j];
        ((float4*)out)[(size_t)b * OUT_T * (SDIM / 4) + s4] = v;
        uint4 o4 = make_uint4(f2tf32(v.x), f2tf32(v.y), f2tf32(v.z), f2tf32(v.w));
        int xmt = b >> 5, bl = b & 31;
        size_t widx = (size_t)xmt * 32768 + (size_t)(s4 & 1) * 16384
                    + (size_t)(s4 >> 1) * 128 + (size_t)bl * 4;
        *(uint4*)(g_xbuf[0] + widx) = o4;
    }

    // ---- weights into registers (invariant across all 512 steps) ----
    uint32_t a[WOCT][4];
    {
        const int srow = n0 + ss * 16 + g;
#pragma unroll
        for (int i = 0; i < WOCT; i++) {
            int k0 = kg * KSLICE + i * 8 + c;
            a[i][0] = f2tf32(wv(A, Bm, srow, k0));
            a[i][1] = f2tf32(wv(A, Bm, srow + 8, k0));
            a[i][2] = f2tf32(wv(A, Bm, srow, k0 + 4));
            a[i][3] = f2tf32(wv(A, Bm, srow + 8, k0 + 4));
        }
    }

    unsigned epoch = base + 1;
    grid_barrier(epoch, bid, tid);
    epoch++;

    const uint16_t mask = (1u << CLUSTER) - 1u;   // 0xF

    for (int t = 0; t < HH; t++) {
        // ---- stage x_t + u_t via multicast bulk (cooperative 1/4 slices) ----
        if (tid == 0) {
            asm volatile("mbarrier.arrive.expect_tx.shared.b64 _, [%0], %1;"
                         :: "r"(mbar), "r"((uint32_t)STEP_TX) : "memory");
            // x slice: rank r copies bytes [r*32768, (r+1)*32768) of the mt block
            {
                const uint32_t* src = g_xbuf[t & 1] + (size_t)mt * 32768 + rank * 8192;
                int half = rank >> 1, part = rank & 1;
                uint32_t dst = smb + half * (XHALF_W * 4) + part * 32768;
                bulk_mc(dst, src, 32768, mbar, mask);
            }
            // u slice: rank r copies bytes [r*4096, (r+1)*4096)
            {
                const uint32_t* src = g_ubuf + ((size_t)t * 4 + mt) * 4096 + rank * 1024;
                int half = rank >> 1, q = rank & 1;
                uint32_t dst = smb + half * (XHALF_W * 4) + 65536 + q * 4096;
                bulk_mc(dst, src, 4096, mbar, mask);
            }
        }
        mbar_wait(mbar, (uint32_t)(t & 1));

        // ---- MMA mainloop: D[s16][b32] over this warp's 288-k slice ----
        float d[4][4];
#pragma unroll
        for (int nn = 0; nn < 4; nn++)
#pragma unroll
            for (int q = 0; q < 4; q++) d[nn][q] = 0.0f;

        const int wbase = kg * (WOCT * 128) + g * 4 + c;
#pragma unroll
        for (int i = 0; i < WOCT; i++) {
#pragma unroll
            for (int nn = 0; nn < 4; nn++) {
                uint32_t blo = sm[wbase + i * 128 + nn * 32];
                uint32_t bhi = sm[wbase + i * 128 + nn * 32 + XHALF_W];
                mma_tf32(d[nn], a[i][0], a[i][1], a[i][2], a[i][3], blo, bhi);
            }
        }

        // ---- partials to smem ----
        {
            int rb = w * (16 * RED_STRIDE) + g * RED_STRIDE + 2 * c;
#pragma unroll
            for (int nn = 0; nn < 4; nn++) {
                *(float2*)(red + rb + nn * 8) = make_float2(d[nn][0], d[nn][1]);
                *(float2*)(red + rb + 8 * RED_STRIDE + nn * 8) = make_float2(d[nn][2], d[nn][3]);
            }
        }
        __syncthreads();

        // ---- reduce 4 k-partials; write fp32 out + tf32 xbuf (MMA layout) ----
        {
            int b = tid >> 3;               // 0..31
            int s4 = (tid & 7) * 4;         // 0,4,..,28
            int ssr = s4 >> 4;
            float acc0 = 0.f, acc1 = 0.f, acc2 = 0.f, acc3 = 0.f;
#pragma unroll
            for (int kk = 0; kk < 4; kk++) {
                int wb = (kk * 2 + ssr) * (16 * RED_STRIDE) + b;
                acc0 += red[wb + ((s4 + 0) & 15) * RED_STRIDE];
                acc1 += red[wb + ((s4 + 1) & 15) * RED_STRIDE];
                acc2 += red[wb + ((s4 + 2) & 15) * RED_STRIDE];
                acc3 += red[wb + ((s4 + 3) & 15) * RED_STRIDE];
            }
            float* op = out + ((size_t)(m0 + b) * OUT_T + (t + 1)) * SDIM + n0 + s4;
            *(float4*)op = make_float4(acc0, acc1, acc2, acc3);

            int k = n0 + s4;
            size_t widx = (size_t)mt * 32768 + (size_t)((k >> 2) & 1) * 16384
                        + (size_t)(k >> 3) * 128 + (size_t)b * 4;
            uint32_t* xp = g_xbuf[(t + 1) & 1] + widx;
            uint32_t t0 = f2tf32(acc0), t1 = f2tf32(acc1), t2 = f2tf32(acc2), t3 = f2tf32(acc3);
            asm volatile("st.global.cg.v4.b32 [%0], {%1,%2,%3,%4};"
                         :: "l"(xp), "r"(t0), "r"(t1), "r"(t2), "r"(t3) : "memory");
        }

        grid_barrier(epoch, bid, tid);
        epoch++;
    }
}

extern "C" void kernel_launch(void* const* d_in, const int* in_sizes, int n_in,
                              void* d_out, int out_size)
{
    const float* x0 = (const float*)d_in[0];
    const float* u  = (const float*)d_in[1];
    const float* A  = (const float*)d_in[2];
    const float* Bm = (const float*)d_in[3];
    float* out = (float*)d_out;

    cudaFuncSetAttribute(ssm_v4_kernel,
                         cudaFuncAttributeMaxDynamicSharedMemorySize, SMEM_BYTES);

    ssm_v4_kernel<<<NCTA, NTHREADS, SMEM_BYTES>>>(x0, u, A, Bm, out);
}